// round 14
// baseline (speedup 1.0000x reference)
#include <cuda_runtime.h>
#include <cstdint>

// TripletEntropyLoss N=8192 D=128 — persistent int8 mma.sync, software-pipelined:
// epilogue(tile t) interleaved into mainloop(tile t+1) so MUFU/FMA overlap tensor.
// Quant x -> round(24x) clamp ±127; int32 dot exact; exp arg = acc * (1/576/4).

#define NROWS 8192
#define DDIM  128
#define TILE  128
#define THREADS 256
#define GRID_P 148          // 1 CTA per SM (reg-heavy: two accumulator sets)
#define NTILES (64 * 64 * 3)

#define DELTA_C 0.001f
#define QSCALE  24.0f
#define ARG_SCALE (0.25f / (QSCALE * QSCALE))
#define ARG_DIAG  (DELTA_C * 0.25f)
#define INV_MAG 0.25f

#define BUF_PAIR 32768      // A(16KB)+B(16KB)
#define SM_TOTAL (2 * BUF_PAIR)

__device__ float g_rowsum[NROWS];
__device__ int8_t g_Aq[NROWS * DDIM];
__device__ int8_t g_Pq[NROWS * DDIM];
__device__ int8_t g_Nq[NROWS * DDIM];

__device__ __forceinline__ uint32_t smem_u32(const void* p) {
    uint32_t a;
    asm("{ .reg .u64 t; cvta.to.shared.u64 t, %1; cvt.u32.u64 %0, t; }" : "=r"(a) : "l"(p));
    return a;
}

#define CP_ASYNC16(dst, src) \
    asm volatile("cp.async.cg.shared.global [%0], [%1], 16;" :: "r"(dst), "l"(src))
#define CP_COMMIT() asm volatile("cp.async.commit_group;")
#define CP_WAIT1()  asm volatile("cp.async.wait_group 1;")
#define CP_WAIT0()  asm volatile("cp.async.wait_group 0;")

#define LDSM_X4(r0, r1, r2, r3, a) \
    asm volatile("ldmatrix.sync.aligned.m8n8.x4.shared.b16 {%0,%1,%2,%3}, [%4];" \
                 : "=r"(r0), "=r"(r1), "=r"(r2), "=r"(r3) : "r"(a))

#define MMA_S8(d, a, b) \
    asm volatile("mma.sync.aligned.m16n8k32.row.col.s32.s8.s8.s32 " \
                 "{%0,%1,%2,%3}, {%4,%5,%6,%7}, {%8,%9}, {%0,%1,%2,%3};" \
                 : "+r"((d)[0]), "+r"((d)[1]), "+r"((d)[2]), "+r"((d)[3]) \
                 : "r"((a)[0]), "r"((a)[1]), "r"((a)[2]), "r"((a)[3]), \
                   "r"((b)[0]), "r"((b)[1]))

__device__ __forceinline__ int8_t quant1(float v) {
    float q = rintf(v * QSCALE);
    q = fminf(fmaxf(q, -127.0f), 127.0f);
    return (int8_t)(int)q;
}

// ---------------- conv + zero (fused) ----------------
__global__ __launch_bounds__(256) void conv_k(const float* __restrict__ A,
                                              const float* __restrict__ P,
                                              const float* __restrict__ Ng,
                                              float* out) {
    int m = blockIdx.y;
    const float* s = (m == 0) ? Ng : ((m == 1) ? P : A);
    int8_t* d = (m == 0) ? g_Nq : ((m == 1) ? g_Pq : g_Aq);
    int i = (blockIdx.x * 256 + threadIdx.x) * 4;
    float4 v = *(const float4*)(s + i);
    char4 q;
    q.x = quant1(v.x); q.y = quant1(v.y); q.z = quant1(v.z); q.w = quant1(v.w);
    *(char4*)(d + i) = q;
    if (m == 0 && blockIdx.x < NROWS / 256)
        g_rowsum[blockIdx.x * 256 + threadIdx.x] = 0.0f;
    if (m == 0 && blockIdx.x == NROWS / 256 && threadIdx.x == 0) out[0] = 0.0f;
}

// ---------------- prefetch ----------------
__device__ __forceinline__ void prefetch_tile(int t, int buf, int tid, uint32_t sm0) {
    int m    = t >> 12;
    int r    = t & 4095;
    int row0 = (r >> 6) * TILE;
    int col0 = (r & 63) * TILE;
    const int8_t* Bsrc = (m == 0) ? g_Nq : ((m == 1) ? g_Pq : g_Aq);
    int lr  = tid >> 1;
    int lc0 = tid & 1;
    int sw  = lr & 7;
    const int8_t* Ag = g_Aq + (size_t)(row0 + lr) * DDIM;
    const int8_t* Bg = Bsrc + (size_t)(col0 + lr) * DDIM;
    uint32_t sA = sm0 + (uint32_t)(buf * BUF_PAIR) + (uint32_t)(lr * 128);
    uint32_t sB = sA + 16384;
#pragma unroll
    for (int c = lc0; c < 8; c += 2) {
        CP_ASYNC16(sA + (uint32_t)((c ^ sw) << 4), Ag + c * 16);
        CP_ASYNC16(sB + (uint32_t)((c ^ sw) << 4), Bg + c * 16);
    }
    CP_COMMIT();
}

// epilogue quarter for row-group MT of the *previous* tile (accums DP)
#define EPI_QUARTER(DP, TP, MT) do {                                          \
    int _r    = (TP) & 4095;                                                  \
    int _m    = (TP) >> 12;                                                   \
    float _coef = (_m == 0) ? 0.5f : 0.25f;                                   \
    bool _md  = (_m >= 1) && ((_r >> 6) == (_r & 63));                        \
    int _row0 = (_r >> 6) * TILE + wm * 64;                                   \
    int _col0 = (_r & 63) * TILE + wn * 32;                                   \
    int _rlo  = _row0 + (MT) * 16 + rl;                                       \
    int _rhi  = _rlo + 8;                                                     \
    float _e0 = 0.0f, _e1 = 0.0f;                                             \
    _Pragma("unroll")                                                         \
    for (int _nt = 0; _nt < 4; _nt++) {                                       \
        int _n0 = _col0 + _nt * 8 + cl;                                       \
        float _v0 = (float)DP[MT][_nt][0] * ARG_SCALE;                        \
        float _v1 = (float)DP[MT][_nt][1] * ARG_SCALE;                        \
        float _v2 = (float)DP[MT][_nt][2] * ARG_SCALE;                        \
        float _v3 = (float)DP[MT][_nt][3] * ARG_SCALE;                        \
        if (_md) {                                                            \
            if (_n0     == _rlo) _v0 = ARG_DIAG;                              \
            if (_n0 + 1 == _rlo) _v1 = ARG_DIAG;                              \
            if (_n0     == _rhi) _v2 = ARG_DIAG;                              \
            if (_n0 + 1 == _rhi) _v3 = ARG_DIAG;                              \
        }                                                                     \
        _e0 += __expf(_v0) + __expf(_v1);                                     \
        _e1 += __expf(_v2) + __expf(_v3);                                     \
    }                                                                         \
    _e0 += __shfl_xor_sync(0xffffffffu, _e0, 1);                              \
    _e0 += __shfl_xor_sync(0xffffffffu, _e0, 2);                              \
    _e1 += __shfl_xor_sync(0xffffffffu, _e1, 1);                              \
    _e1 += __shfl_xor_sync(0xffffffffu, _e1, 2);                              \
    if ((lane & 3) == 0) {                                                    \
        atomicAdd(&g_rowsum[_rlo], _coef * _e0);                              \
        atomicAdd(&g_rowsum[_rhi], _coef * _e1);                              \
    }                                                                         \
} while (0)

// one pipeline step: mainloop(TC -> DC) interleaved with epilogue(tprev via DP)
#define TILE_STEP(TC, DC, DP) do {                                            \
    bool act = (TC) < NTILES;                                                 \
    int tn = (TC) + GRID_P;                                                   \
    if (act) {                                                                \
        if (tn < NTILES) prefetch_tile(tn, pbuf ^ 1, tid, sm0);               \
        if (tn < NTILES) { CP_WAIT1(); } else { CP_WAIT0(); }                 \
        __syncthreads();                                                      \
    }                                                                         \
    uint32_t sAu = sm0 + (uint32_t)(pbuf * BUF_PAIR);                         \
    uint32_t sBu = sAu + 16384;                                               \
    if (act) {                                                                \
        _Pragma("unroll")                                                     \
        for (int mt = 0; mt < 4; mt++)                                        \
            _Pragma("unroll")                                                 \
            for (int nt = 0; nt < 4; nt++)                                    \
                _Pragma("unroll")                                             \
                for (int v = 0; v < 4; v++) DC[mt][nt][v] = 0;                \
    }                                                                         \
    _Pragma("unroll")                                                         \
    for (int ks = 0; ks < 4; ks++) {                                          \
        if (act) {                                                            \
            uint32_t a[4][4], b[4][2];                                        \
            _Pragma("unroll")                                                 \
            for (int mt = 0; mt < 4; mt++) {                                  \
                uint32_t addr = sAu + (uint32_t)((rA + mt * 16) * 128)        \
                              + (uint32_t)(((ks * 2 + halfA) ^ a7) << 4);     \
                LDSM_X4(a[mt][0], a[mt][1], a[mt][2], a[mt][3], addr);        \
            }                                                                 \
            _Pragma("unroll")                                                 \
            for (int p = 0; p < 2; p++) {                                     \
                uint32_t addr = sBu + (uint32_t)((rB + p * 16) * 128)         \
                              + (uint32_t)(((ks * 2 + halfB) ^ b7) << 4);     \
                LDSM_X4(b[2*p][0], b[2*p][1], b[2*p+1][0], b[2*p+1][1], addr);\
            }                                                                 \
            _Pragma("unroll")                                                 \
            for (int mt = 0; mt < 4; mt++)                                    \
                _Pragma("unroll")                                             \
                for (int nt = 0; nt < 4; nt++)                                \
                    MMA_S8(DC[mt][nt], a[mt], b[nt]);                         \
        }                                                                     \
        if (tprev >= 0) EPI_QUARTER(DP, tprev, ks);                           \
    }                                                                         \
    if (act) __syncthreads();                                                 \
    tprev = act ? (TC) : -1;                                                  \
    if (act) pbuf ^= 1;                                                       \
} while (0)

__global__ __launch_bounds__(THREADS, 1) void gemm_exp_mma() {
    extern __shared__ char smem[];
    uint32_t sm0 = smem_u32(smem);

    int tid  = threadIdx.x;
    int lane = tid & 31;
    int wid  = tid >> 5;
    int wm   = wid >> 2;
    int wn   = wid & 3;

    int rA    = wm * 64 + (lane & 15);
    int halfA = lane >> 4;
    int a7    = rA & 7;
    int rB    = wn * 32 + ((lane >> 4) & 1) * 8 + (lane & 7);
    int halfB = (lane >> 3) & 1;
    int b7    = lane & 7;
    int rl = lane >> 2;
    int cl = (lane & 3) * 2;

    int d0[4][4][4], d1[4][4][4];
    int t0    = blockIdx.x;
    int tprev = -1;
    int pbuf  = 0;

    prefetch_tile(t0, 0, tid, sm0);

    // paired steps (ping-pong accumulators); extra trailing steps drain epilogue
    for (int t = t0; t < NTILES + 2 * GRID_P; t += 2 * GRID_P) {
        TILE_STEP(t, d0, d1);
        TILE_STEP(t + GRID_P, d1, d0);
    }
}

// ---------------- finalize: one warp per row (fp32 pos_sim) ----------------
__global__ __launch_bounds__(256) void finalize_k(const float* __restrict__ A,
                                                  const float* __restrict__ P,
                                                  float* out) {
    int tid  = threadIdx.x;
    int lane = tid & 31;
    int wid  = tid >> 5;
    int row  = blockIdx.x * 8 + wid;

    float4 a = *(const float4*)(A + (size_t)row * DDIM + lane * 4);
    float4 p = *(const float4*)(P + (size_t)row * DDIM + lane * 4);
    float dsum = a.x * p.x + a.y * p.y + a.z * p.z + a.w * p.w;
#pragma unroll
    for (int off = 16; off > 0; off >>= 1)
        dsum += __shfl_xor_sync(0xffffffffu, dsum, off);

    __shared__ float sh[8];
    if (lane == 0) {
        float v = logf(g_rowsum[row]) - dsum * INV_MAG;
        sh[wid] = v > 0.0f ? v : 0.0f;
    }
    __syncthreads();
    if (tid == 0) {
        float s = sh[0] + sh[1] + sh[2] + sh[3] + sh[4] + sh[5] + sh[6] + sh[7];
        atomicAdd(out, s * (1.0f / NROWS));
    }
}

extern "C" void kernel_launch(void* const* d_in, const int* in_sizes, int n_in,
                              void* d_out, int out_size) {
    const float* A  = (const float*)d_in[0];
    const float* P  = (const float*)d_in[1];
    const float* Ng = (const float*)d_in[2];
    float* out = (float*)d_out;

    static int smem_set = 0;
    if (!smem_set) {
        cudaFuncSetAttribute(gemm_exp_mma, cudaFuncAttributeMaxDynamicSharedMemorySize,
                             SM_TOTAL);
        smem_set = 1;
    }

    dim3 cg(NROWS * DDIM / 4 / 256, 3);          // (1024, 3)
    conv_k<<<cg, 256>>>(A, P, Ng, out);
    gemm_exp_mma<<<GRID_P, THREADS, SM_TOTAL>>>();
    finalize_k<<<NROWS / 8, 256>>>(A, P, out);   // 1024 blocks, warp per row
}

// round 15
// speedup vs baseline: 1.2525x; 1.2525x over previous
#include <cuda_runtime.h>
#include <cstdint>

// TripletEntropyLoss N=8192 D=128 — persistent int8 mma.sync, triple-buffered
// cp.async (depth 2), ONE barrier per tile, per-strip fused epilogue so warps
// self-stagger and tensor/MUFU/LDSM pipes overlap.
// Quant x -> round(24x) clamp ±127; int32 dot exact; exp arg = acc * (1/576/4).

#define NROWS 8192
#define DDIM  128
#define TILE  128
#define THREADS 256
#define GRID_P 296          // 2 CTAs per SM
#define NTILES (64 * 64 * 3)

#define DELTA_C 0.001f
#define QSCALE  24.0f
#define ARG_SCALE (0.25f / (QSCALE * QSCALE))
#define ARG_DIAG  (DELTA_C * 0.25f)
#define INV_MAG 0.25f

#define BUF_PAIR 32768              // A(16KB)+B(16KB)
#define SM_TOTAL (3 * BUF_PAIR)     // triple-buffered ring: 96KB

__device__ float g_rowsum[NROWS];
__device__ int8_t g_Aq[NROWS * DDIM];
__device__ int8_t g_Pq[NROWS * DDIM];
__device__ int8_t g_Nq[NROWS * DDIM];

__device__ __forceinline__ uint32_t smem_u32(const void* p) {
    uint32_t a;
    asm("{ .reg .u64 t; cvta.to.shared.u64 t, %1; cvt.u32.u64 %0, t; }" : "=r"(a) : "l"(p));
    return a;
}

#define CP_ASYNC16(dst, src) \
    asm volatile("cp.async.cg.shared.global [%0], [%1], 16;" :: "r"(dst), "l"(src))
#define CP_COMMIT() asm volatile("cp.async.commit_group;")
#define CP_WAIT1()  asm volatile("cp.async.wait_group 1;")
#define CP_WAIT0()  asm volatile("cp.async.wait_group 0;")

#define LDSM_X4(r0, r1, r2, r3, a) \
    asm volatile("ldmatrix.sync.aligned.m8n8.x4.shared.b16 {%0,%1,%2,%3}, [%4];" \
                 : "=r"(r0), "=r"(r1), "=r"(r2), "=r"(r3) : "r"(a))

#define MMA_S8(d, a, b) \
    asm volatile("mma.sync.aligned.m16n8k32.row.col.s32.s8.s8.s32 " \
                 "{%0,%1,%2,%3}, {%4,%5,%6,%7}, {%8,%9}, {%0,%1,%2,%3};" \
                 : "+r"((d)[0]), "+r"((d)[1]), "+r"((d)[2]), "+r"((d)[3]) \
                 : "r"((a)[0]), "r"((a)[1]), "r"((a)[2]), "r"((a)[3]), \
                   "r"((b)[0]), "r"((b)[1]))

__device__ __forceinline__ int8_t quant1(float v) {
    float q = rintf(v * QSCALE);
    q = fminf(fmaxf(q, -127.0f), 127.0f);
    return (int8_t)(int)q;
}

// ---------------- conv + zero (fused) ----------------
__global__ __launch_bounds__(256) void conv_k(const float* __restrict__ A,
                                              const float* __restrict__ P,
                                              const float* __restrict__ Ng,
                                              float* out) {
    int m = blockIdx.y;
    const float* s = (m == 0) ? Ng : ((m == 1) ? P : A);
    int8_t* d = (m == 0) ? g_Nq : ((m == 1) ? g_Pq : g_Aq);
    int i = (blockIdx.x * 256 + threadIdx.x) * 4;
    float4 v = *(const float4*)(s + i);
    char4 q;
    q.x = quant1(v.x); q.y = quant1(v.y); q.z = quant1(v.z); q.w = quant1(v.w);
    *(char4*)(d + i) = q;
    if (m == 0 && blockIdx.x < NROWS / 256)
        g_rowsum[blockIdx.x * 256 + threadIdx.x] = 0.0f;
    if (m == 0 && blockIdx.x == NROWS / 256 && threadIdx.x == 0) out[0] = 0.0f;
}

// ---------------- prefetch (one 32KB A+B pair into ring slot buf) ----------
__device__ __forceinline__ void prefetch_tile(int t, int buf, int tid, uint32_t sm0) {
    int m    = t >> 12;
    int r    = t & 4095;
    int row0 = (r >> 6) * TILE;
    int col0 = (r & 63) * TILE;
    const int8_t* Bsrc = (m == 0) ? g_Nq : ((m == 1) ? g_Pq : g_Aq);
    int lr  = tid >> 1;
    int lc0 = tid & 1;
    int sw  = lr & 7;
    const int8_t* Ag = g_Aq + (size_t)(row0 + lr) * DDIM;
    const int8_t* Bg = Bsrc + (size_t)(col0 + lr) * DDIM;
    uint32_t sA = sm0 + (uint32_t)(buf * BUF_PAIR) + (uint32_t)(lr * 128);
    uint32_t sB = sA + 16384;
#pragma unroll
    for (int c = lc0; c < 8; c += 2) {
        CP_ASYNC16(sA + (uint32_t)((c ^ sw) << 4), Ag + c * 16);
        CP_ASYNC16(sB + (uint32_t)((c ^ sw) << 4), Bg + c * 16);
    }
    CP_COMMIT();
}

// ---------------- per-row-group epilogue (16 rows of one mt) ----------------
__device__ __forceinline__ void epi_quarter(const int acc[4][4], int mt,
                                            int warp_row0, int warp_col0,
                                            float coef, bool md,
                                            int rl, int cl, int lane) {
    int r_lo = warp_row0 + mt * 16 + rl;
    int r_hi = r_lo + 8;
    float e0 = 0.0f, e1 = 0.0f;
#pragma unroll
    for (int nt = 0; nt < 4; nt++) {
        int n0 = warp_col0 + nt * 8 + cl;
        float v0 = (float)acc[nt][0] * ARG_SCALE;
        float v1 = (float)acc[nt][1] * ARG_SCALE;
        float v2 = (float)acc[nt][2] * ARG_SCALE;
        float v3 = (float)acc[nt][3] * ARG_SCALE;
        if (md) {
            if (n0     == r_lo) v0 = ARG_DIAG;
            if (n0 + 1 == r_lo) v1 = ARG_DIAG;
            if (n0     == r_hi) v2 = ARG_DIAG;
            if (n0 + 1 == r_hi) v3 = ARG_DIAG;
        }
        e0 += __expf(v0) + __expf(v1);
        e1 += __expf(v2) + __expf(v3);
    }
    e0 += __shfl_xor_sync(0xffffffffu, e0, 1);
    e0 += __shfl_xor_sync(0xffffffffu, e0, 2);
    e1 += __shfl_xor_sync(0xffffffffu, e1, 1);
    e1 += __shfl_xor_sync(0xffffffffu, e1, 2);
    if ((lane & 3) == 0) {
        atomicAdd(&g_rowsum[r_lo], coef * e0);
        atomicAdd(&g_rowsum[r_hi], coef * e1);
    }
}

// ---------------- persistent GEMM+exp kernel ----------------
__global__ __launch_bounds__(THREADS) void gemm_exp_mma() {
    extern __shared__ char smem[];
    uint32_t sm0 = smem_u32(smem);

    int tid  = threadIdx.x;
    int lane = tid & 31;
    int wid  = tid >> 5;
    int wm   = wid >> 2;
    int wn   = wid & 3;

    int rA    = wm * 64 + (lane & 15);
    int halfA = lane >> 4;
    int a7    = rA & 7;
    int rB    = wn * 32 + ((lane >> 4) & 1) * 8 + (lane & 7);
    int halfB = (lane >> 3) & 1;
    int b7    = lane & 7;
    int rl = lane >> 2;
    int cl = (lane & 3) * 2;

    int t0 = blockIdx.x;
    prefetch_tile(t0, 0, tid, sm0);
    if (t0 + GRID_P < NTILES) prefetch_tile(t0 + GRID_P, 1, tid, sm0);

    int bufc = 0;
    for (int t = t0; t < NTILES; t += GRID_P) {
        // wait for tile t's data (keep the next tile's group in flight)
        if (t + GRID_P < NTILES) { CP_WAIT1(); } else { CP_WAIT0(); }
        __syncthreads();    // t's data visible to all; slot (bufc+2)%3 free
        int t2 = t + 2 * GRID_P;
        if (t2 < NTILES) prefetch_tile(t2, (bufc + 2) % 3, tid, sm0);

        uint32_t sAu = sm0 + (uint32_t)(bufc * BUF_PAIR);
        uint32_t sBu = sAu + 16384;

        int m    = t >> 12;
        int r    = t & 4095;
        float coef = (m == 0) ? 0.5f : 0.25f;
        bool md = (m >= 1) && ((r >> 6) == (r & 63));
        int warp_row0 = (r >> 6) * TILE + wm * 64;
        int warp_col0 = (r & 63) * TILE + wn * 32;

        // two strips (mt-pairs); each strip: 16 MMAs then its fused epilogue.
        // No trailing barrier: warps free-run into the next strip/tile body.
#pragma unroll
        for (int s = 0; s < 2; s++) {
            int acc[2][4][4];
#pragma unroll
            for (int mh = 0; mh < 2; mh++)
#pragma unroll
                for (int nt = 0; nt < 4; nt++)
#pragma unroll
                    for (int v = 0; v < 4; v++) acc[mh][nt][v] = 0;

#pragma unroll
            for (int ks = 0; ks < 4; ks++) {
                uint32_t a[2][4], b[4][2];
#pragma unroll
                for (int mh = 0; mh < 2; mh++) {
                    int mt = s * 2 + mh;
                    uint32_t addr = sAu + (uint32_t)((rA + mt * 16) * 128)
                                  + (uint32_t)(((ks * 2 + halfA) ^ a7) << 4);
                    LDSM_X4(a[mh][0], a[mh][1], a[mh][2], a[mh][3], addr);
                }
#pragma unroll
                for (int p = 0; p < 2; p++) {
                    uint32_t addr = sBu + (uint32_t)((rB + p * 16) * 128)
                                  + (uint32_t)(((ks * 2 + halfB) ^ b7) << 4);
                    LDSM_X4(b[2*p][0], b[2*p][1], b[2*p+1][0], b[2*p+1][1], addr);
                }
#pragma unroll
                for (int mh = 0; mh < 2; mh++)
#pragma unroll
                    for (int nt = 0; nt < 4; nt++)
                        MMA_S8(acc[mh][nt], a[mh], b[nt]);
            }
#pragma unroll
            for (int mh = 0; mh < 2; mh++)
                epi_quarter(acc[mh], s * 2 + mh, warp_row0, warp_col0,
                            coef, md, rl, cl, lane);
        }
        bufc = (bufc == 2) ? 0 : bufc + 1;
    }
}

// ---------------- finalize: one warp per row (fp32 pos_sim) ----------------
__global__ __launch_bounds__(256) void finalize_k(const float* __restrict__ A,
                                                  const float* __restrict__ P,
                                                  float* out) {
    int tid  = threadIdx.x;
    int lane = tid & 31;
    int wid  = tid >> 5;
    int row  = blockIdx.x * 8 + wid;

    float4 a = *(const float4*)(A + (size_t)row * DDIM + lane * 4);
    float4 p = *(const float4*)(P + (size_t)row * DDIM + lane * 4);
    float dsum = a.x * p.x + a.y * p.y + a.z * p.z + a.w * p.w;
#pragma unroll
    for (int off = 16; off > 0; off >>= 1)
        dsum += __shfl_xor_sync(0xffffffffu, dsum, off);

    __shared__ float sh[8];
    if (lane == 0) {
        float v = logf(g_rowsum[row]) - dsum * INV_MAG;
        sh[wid] = v > 0.0f ? v : 0.0f;
    }
    __syncthreads();
    if (tid == 0) {
        float s = sh[0] + sh[1] + sh[2] + sh[3] + sh[4] + sh[5] + sh[6] + sh[7];
        atomicAdd(out, s * (1.0f / NROWS));
    }
}

extern "C" void kernel_launch(void* const* d_in, const int* in_sizes, int n_in,
                              void* d_out, int out_size) {
    const float* A  = (const float*)d_in[0];
    const float* P  = (const float*)d_in[1];
    const float* Ng = (const float*)d_in[2];
    float* out = (float*)d_out;

    static int smem_set = 0;
    if (!smem_set) {
        cudaFuncSetAttribute(gemm_exp_mma, cudaFuncAttributeMaxDynamicSharedMemorySize,
                             SM_TOTAL);
        smem_set = 1;
    }

    dim3 cg(NROWS * DDIM / 4 / 256, 3);          // (1024, 3)
    conv_k<<<cg, 256>>>(A, P, Ng, out);
    gemm_exp_mma<<<GRID_P, THREADS, SM_TOTAL>>>();
    finalize_k<<<NROWS / 8, 256>>>(A, P, out);   // 1024 blocks, warp per row
}

// round 16
// speedup vs baseline: 1.2956x; 1.0345x over previous
#include <cuda_runtime.h>
#include <cstdint>

// TripletEntropyLoss N=8192 D=128 — persistent int8 mma.sync, triple-buffered
// cp.async, one barrier per tile. Epilogue avoids I2F via magic-number int->float
// (IADD on ALU pipe) + single FFMA folding (unbias, dequant, log2e) -> MUFU.EX2.
// Quant x -> round(24x) clamp ±127; int32 dot exact.

#define NROWS 8192
#define DDIM  128
#define TILE  128
#define THREADS 256
#define GRID_P 296          // 2 CTAs per SM
#define NTILES (64 * 64 * 3)

#define DELTA_C 0.001f
#define QSCALE  24.0f
#define ARG_SCALE (0.25f / (QSCALE * QSCALE))     // dequant * (1/MAGNITUDE)
#define LOG2E 1.4426950408889634f
#define S2    (ARG_SCALE * LOG2E)                 // exp2 scale
#define MAGICF 12582912.0f                        // 1.5 * 2^23
#define C2    (-(MAGICF * S2))
#define DIAG2 (DELTA_C * 0.25f * LOG2E)
#define INV_MAG 0.25f

#define BUF_PAIR 32768              // A(16KB)+B(16KB)
#define SM_TOTAL (3 * BUF_PAIR)     // triple-buffered ring: 96KB

__device__ float g_rowsum[NROWS];
__device__ int8_t g_Aq[NROWS * DDIM];
__device__ int8_t g_Pq[NROWS * DDIM];
__device__ int8_t g_Nq[NROWS * DDIM];

__device__ __forceinline__ uint32_t smem_u32(const void* p) {
    uint32_t a;
    asm("{ .reg .u64 t; cvta.to.shared.u64 t, %1; cvt.u32.u64 %0, t; }" : "=r"(a) : "l"(p));
    return a;
}

#define CP_ASYNC16(dst, src) \
    asm volatile("cp.async.cg.shared.global [%0], [%1], 16;" :: "r"(dst), "l"(src))
#define CP_COMMIT() asm volatile("cp.async.commit_group;")
#define CP_WAIT1()  asm volatile("cp.async.wait_group 1;")
#define CP_WAIT0()  asm volatile("cp.async.wait_group 0;")

#define LDSM_X4(r0, r1, r2, r3, a) \
    asm volatile("ldmatrix.sync.aligned.m8n8.x4.shared.b16 {%0,%1,%2,%3}, [%4];" \
                 : "=r"(r0), "=r"(r1), "=r"(r2), "=r"(r3) : "r"(a))

#define MMA_S8(d, a, b) \
    asm volatile("mma.sync.aligned.m16n8k32.row.col.s32.s8.s8.s32 " \
                 "{%0,%1,%2,%3}, {%4,%5,%6,%7}, {%8,%9}, {%0,%1,%2,%3};" \
                 : "+r"((d)[0]), "+r"((d)[1]), "+r"((d)[2]), "+r"((d)[3]) \
                 : "r"((a)[0]), "r"((a)[1]), "r"((a)[2]), "r"((a)[3]), \
                   "r"((b)[0]), "r"((b)[1]))

__device__ __forceinline__ int8_t quant1(float v) {
    float q = rintf(v * QSCALE);
    q = fminf(fmaxf(q, -127.0f), 127.0f);
    return (int8_t)(int)q;
}

// magic int->float + fold: returns exp2 argument = acc*ARG_SCALE*log2e
__device__ __forceinline__ float acc2arg(int acc) {
    uint32_t bits = (uint32_t)acc + 0x4B400000u;   // IADD (ALU pipe)
    return fmaf(__uint_as_float(bits), S2, C2);    // FFMA (FMA pipe)
}

// ---------------- conv + zero (fused) ----------------
__global__ __launch_bounds__(256) void conv_k(const float* __restrict__ A,
                                              const float* __restrict__ P,
                                              const float* __restrict__ Ng,
                                              float* out) {
    int m = blockIdx.y;
    const float* s = (m == 0) ? Ng : ((m == 1) ? P : A);
    int8_t* d = (m == 0) ? g_Nq : ((m == 1) ? g_Pq : g_Aq);
    int i = (blockIdx.x * 256 + threadIdx.x) * 4;
    float4 v = *(const float4*)(s + i);
    char4 q;
    q.x = quant1(v.x); q.y = quant1(v.y); q.z = quant1(v.z); q.w = quant1(v.w);
    *(char4*)(d + i) = q;
    if (m == 0 && blockIdx.x < NROWS / 256)
        g_rowsum[blockIdx.x * 256 + threadIdx.x] = 0.0f;
    if (m == 0 && blockIdx.x == NROWS / 256 && threadIdx.x == 0) out[0] = 0.0f;
}

// ---------------- prefetch (one 32KB A+B pair into ring slot buf) ----------
__device__ __forceinline__ void prefetch_tile(int t, int buf, int tid, uint32_t sm0) {
    int m    = t >> 12;
    int r    = t & 4095;
    int row0 = (r >> 6) * TILE;
    int col0 = (r & 63) * TILE;
    const int8_t* Bsrc = (m == 0) ? g_Nq : ((m == 1) ? g_Pq : g_Aq);
    int lr  = tid >> 1;
    int lc0 = tid & 1;
    int sw  = lr & 7;
    const int8_t* Ag = g_Aq + (size_t)(row0 + lr) * DDIM;
    const int8_t* Bg = Bsrc + (size_t)(col0 + lr) * DDIM;
    uint32_t sA = sm0 + (uint32_t)(buf * BUF_PAIR) + (uint32_t)(lr * 128);
    uint32_t sB = sA + 16384;
#pragma unroll
    for (int c = lc0; c < 8; c += 2) {
        CP_ASYNC16(sA + (uint32_t)((c ^ sw) << 4), Ag + c * 16);
        CP_ASYNC16(sB + (uint32_t)((c ^ sw) << 4), Bg + c * 16);
    }
    CP_COMMIT();
}

// ---------------- per-row-group epilogue (16 rows of one mt) ----------------
__device__ __forceinline__ void epi_quarter(const int acc[4][4], int mt,
                                            int warp_row0, int warp_col0,
                                            float coef, bool md,
                                            int rl, int cl, int lane) {
    int r_lo = warp_row0 + mt * 16 + rl;
    int r_hi = r_lo + 8;
    float e0 = 0.0f, e1 = 0.0f;
#pragma unroll
    for (int nt = 0; nt < 4; nt++) {
        int n0 = warp_col0 + nt * 8 + cl;
        float a0 = acc2arg(acc[nt][0]);
        float a1 = acc2arg(acc[nt][1]);
        float a2 = acc2arg(acc[nt][2]);
        float a3 = acc2arg(acc[nt][3]);
        if (md) {
            if (n0     == r_lo) a0 = DIAG2;
            if (n0 + 1 == r_lo) a1 = DIAG2;
            if (n0     == r_hi) a2 = DIAG2;
            if (n0 + 1 == r_hi) a3 = DIAG2;
        }
        e0 += exp2f(a0) + exp2f(a1);
        e1 += exp2f(a2) + exp2f(a3);
    }
    e0 += __shfl_xor_sync(0xffffffffu, e0, 1);
    e0 += __shfl_xor_sync(0xffffffffu, e0, 2);
    e1 += __shfl_xor_sync(0xffffffffu, e1, 1);
    e1 += __shfl_xor_sync(0xffffffffu, e1, 2);
    if ((lane & 3) == 0) {
        atomicAdd(&g_rowsum[r_lo], coef * e0);
        atomicAdd(&g_rowsum[r_hi], coef * e1);
    }
}

// ---------------- persistent GEMM+exp kernel ----------------
__global__ __launch_bounds__(THREADS) void gemm_exp_mma() {
    extern __shared__ char smem[];
    uint32_t sm0 = smem_u32(smem);

    int tid  = threadIdx.x;
    int lane = tid & 31;
    int wid  = tid >> 5;
    int wm   = wid >> 2;
    int wn   = wid & 3;

    int rA    = wm * 64 + (lane & 15);
    int halfA = lane >> 4;
    int a7    = rA & 7;
    int rB    = wn * 32 + ((lane >> 4) & 1) * 8 + (lane & 7);
    int halfB = (lane >> 3) & 1;
    int b7    = lane & 7;
    int rl = lane >> 2;
    int cl = (lane & 3) * 2;

    int t0 = blockIdx.x;
    prefetch_tile(t0, 0, tid, sm0);
    if (t0 + GRID_P < NTILES) prefetch_tile(t0 + GRID_P, 1, tid, sm0);

    int bufc = 0;
    for (int t = t0; t < NTILES; t += GRID_P) {
        if (t + GRID_P < NTILES) { CP_WAIT1(); } else { CP_WAIT0(); }
        __syncthreads();    // t's data visible; slot (bufc+2)%3 free
        int t2 = t + 2 * GRID_P;
        if (t2 < NTILES) prefetch_tile(t2, (bufc + 2) % 3, tid, sm0);

        uint32_t sAu = sm0 + (uint32_t)(bufc * BUF_PAIR);
        uint32_t sBu = sAu + 16384;

        int m    = t >> 12;
        int r    = t & 4095;
        float coef = (m == 0) ? 0.5f : 0.25f;
        bool md = (m >= 1) && ((r >> 6) == (r & 63));
        int warp_row0 = (r >> 6) * TILE + wm * 64;
        int warp_col0 = (r & 63) * TILE + wn * 32;

#pragma unroll
        for (int s = 0; s < 2; s++) {
            int acc[2][4][4];
#pragma unroll
            for (int mh = 0; mh < 2; mh++)
#pragma unroll
                for (int nt = 0; nt < 4; nt++)
#pragma unroll
                    for (int v = 0; v < 4; v++) acc[mh][nt][v] = 0;

#pragma unroll
            for (int ks = 0; ks < 4; ks++) {
                uint32_t a[2][4], b[4][2];
#pragma unroll
                for (int mh = 0; mh < 2; mh++) {
                    int mt = s * 2 + mh;
                    uint32_t addr = sAu + (uint32_t)((rA + mt * 16) * 128)
                                  + (uint32_t)(((ks * 2 + halfA) ^ a7) << 4);
                    LDSM_X4(a[mh][0], a[mh][1], a[mh][2], a[mh][3], addr);
                }
#pragma unroll
                for (int p = 0; p < 2; p++) {
                    uint32_t addr = sBu + (uint32_t)((rB + p * 16) * 128)
                                  + (uint32_t)(((ks * 2 + halfB) ^ b7) << 4);
                    LDSM_X4(b[2*p][0], b[2*p][1], b[2*p+1][0], b[2*p+1][1], addr);
                }
#pragma unroll
                for (int mh = 0; mh < 2; mh++)
#pragma unroll
                    for (int nt = 0; nt < 4; nt++)
                        MMA_S8(acc[mh][nt], a[mh], b[nt]);
            }
#pragma unroll
            for (int mh = 0; mh < 2; mh++)
                epi_quarter(acc[mh], s * 2 + mh, warp_row0, warp_col0,
                            coef, md, rl, cl, lane);
        }
        bufc = (bufc == 2) ? 0 : bufc + 1;
    }
}

// ---------------- finalize: one warp per row (fp32 pos_sim) ----------------
__global__ __launch_bounds__(256) void finalize_k(const float* __restrict__ A,
                                                  const float* __restrict__ P,
                                                  float* out) {
    int tid  = threadIdx.x;
    int lane = tid & 31;
    int wid  = tid >> 5;
    int row  = blockIdx.x * 8 + wid;

    float4 a = *(const float4*)(A + (size_t)row * DDIM + lane * 4);
    float4 p = *(const float4*)(P + (size_t)row * DDIM + lane * 4);
    float dsum = a.x * p.x + a.y * p.y + a.z * p.z + a.w * p.w;
#pragma unroll
    for (int off = 16; off > 0; off >>= 1)
        dsum += __shfl_xor_sync(0xffffffffu, dsum, off);

    __shared__ float sh[8];
    if (lane == 0) {
        float v = logf(g_rowsum[row]) - dsum * INV_MAG;
        sh[wid] = v > 0.0f ? v : 0.0f;
    }
    __syncthreads();
    if (tid == 0) {
        float s = sh[0] + sh[1] + sh[2] + sh[3] + sh[4] + sh[5] + sh[6] + sh[7];
        atomicAdd(out, s * (1.0f / NROWS));
    }
}

extern "C" void kernel_launch(void* const* d_in, const int* in_sizes, int n_in,
                              void* d_out, int out_size) {
    const float* A  = (const float*)d_in[0];
    const float* P  = (const float*)d_in[1];
    const float* Ng = (const float*)d_in[2];
    float* out = (float*)d_out;

    static int smem_set = 0;
    if (!smem_set) {
        cudaFuncSetAttribute(gemm_exp_mma, cudaFuncAttributeMaxDynamicSharedMemorySize,
                             SM_TOTAL);
        smem_set = 1;
    }

    dim3 cg(NROWS * DDIM / 4 / 256, 3);          // (1024, 3)
    conv_k<<<cg, 256>>>(A, P, Ng, out);
    gemm_exp_mma<<<GRID_P, THREADS, SM_TOTAL>>>();
    finalize_k<<<NROWS / 8, 256>>>(A, P, out);   // 1024 blocks, warp per row
}

// round 17
// speedup vs baseline: 1.4099x; 1.0882x over previous
#include <cuda_runtime.h>
#include <cstdint>

// TripletEntropyLoss N=8192 D=128 — persistent int8 mma.sync, triple-buffered
// cp.async, magic-number I2F-free epilogue, AND anchor-matrix symmetry:
// A·Aᵀ upper-triangular tiles only; off-diag tiles add row-sums (bx block)
// and col-sums (by block). 12288 -> 10272 tiles (-16.4% of all work).
// Quant x -> round(24x) clamp ±127; int32 dot exact.

#define NROWS 8192
#define DDIM  128
#define TILE  128
#define THREADS 256
#define GRID_P 296          // 2 CTAs per SM
#define NT_SQ  4096         // tiles per full matrix (64x64)
#define NT_TRI 2080         // upper-tri incl diagonal (64*65/2)
#define NTILES (2 * NT_SQ + NT_TRI)   // 10272

#define DELTA_C 0.001f
#define QSCALE  24.0f
#define ARG_SCALE (0.25f / (QSCALE * QSCALE))
#define LOG2E 1.4426950408889634f
#define S2    (ARG_SCALE * LOG2E)
#define MAGICF 12582912.0f
#define C2    (-(MAGICF * S2))
#define DIAG2 (DELTA_C * 0.25f * LOG2E)
#define INV_MAG 0.25f

#define BUF_PAIR 32768
#define SM_TOTAL (3 * BUF_PAIR)

__device__ float g_rowsum[NROWS];
__device__ int8_t g_Aq[NROWS * DDIM];
__device__ int8_t g_Pq[NROWS * DDIM];
__device__ int8_t g_Nq[NROWS * DDIM];

__device__ __forceinline__ uint32_t smem_u32(const void* p) {
    uint32_t a;
    asm("{ .reg .u64 t; cvta.to.shared.u64 t, %1; cvt.u32.u64 %0, t; }" : "=r"(a) : "l"(p));
    return a;
}

#define CP_ASYNC16(dst, src) \
    asm volatile("cp.async.cg.shared.global [%0], [%1], 16;" :: "r"(dst), "l"(src))
#define CP_COMMIT() asm volatile("cp.async.commit_group;")
#define CP_WAIT1()  asm volatile("cp.async.wait_group 1;")
#define CP_WAIT0()  asm volatile("cp.async.wait_group 0;")

#define LDSM_X4(r0, r1, r2, r3, a) \
    asm volatile("ldmatrix.sync.aligned.m8n8.x4.shared.b16 {%0,%1,%2,%3}, [%4];" \
                 : "=r"(r0), "=r"(r1), "=r"(r2), "=r"(r3) : "r"(a))

#define MMA_S8(d, a, b) \
    asm volatile("mma.sync.aligned.m16n8k32.row.col.s32.s8.s8.s32 " \
                 "{%0,%1,%2,%3}, {%4,%5,%6,%7}, {%8,%9}, {%0,%1,%2,%3};" \
                 : "+r"((d)[0]), "+r"((d)[1]), "+r"((d)[2]), "+r"((d)[3]) \
                 : "r"((a)[0]), "r"((a)[1]), "r"((a)[2]), "r"((a)[3]), \
                   "r"((b)[0]), "r"((b)[1]))

__device__ __forceinline__ int8_t quant1(float v) {
    float q = rintf(v * QSCALE);
    q = fminf(fmaxf(q, -127.0f), 127.0f);
    return (int8_t)(int)q;
}

__device__ __forceinline__ float acc2arg(int acc) {
    uint32_t bits = (uint32_t)acc + 0x4B400000u;   // IADD (ALU)
    return fmaf(__uint_as_float(bits), S2, C2);    // FFMA
}

// tile decode: t<8192 -> m=t>>12, (bx,by) dense 64x64.
// t>=8192 -> anchor upper-tri pair u = t-8192: bx triangular-inverse, by>=bx.
__device__ __forceinline__ void tdec(int t, int& m, int& bx, int& by) {
    if (t < 2 * NT_SQ) {
        m = t >> 12;
        int r = t & 4095;
        bx = r >> 6;
        by = r & 63;
    } else {
        m = 2;
        int u = t - 2 * NT_SQ;
        int b = (int)(64.5f - sqrtf(4160.25f - 2.0f * (float)u));
        while (64 * b - (b * (b - 1)) / 2 > u) b--;
        while (64 * (b + 1) - ((b + 1) * b) / 2 <= u) b++;
        bx = b;
        by = b + (u - (64 * b - (b * (b - 1)) / 2));
    }
}

// ---------------- conv + zero (fused) ----------------
__global__ __launch_bounds__(256) void conv_k(const float* __restrict__ A,
                                              const float* __restrict__ P,
                                              const float* __restrict__ Ng,
                                              float* out) {
    int m = blockIdx.y;
    const float* s = (m == 0) ? Ng : ((m == 1) ? P : A);
    int8_t* d = (m == 0) ? g_Nq : ((m == 1) ? g_Pq : g_Aq);
    int i = (blockIdx.x * 256 + threadIdx.x) * 4;
    float4 v = *(const float4*)(s + i);
    char4 q;
    q.x = quant1(v.x); q.y = quant1(v.y); q.z = quant1(v.z); q.w = quant1(v.w);
    *(char4*)(d + i) = q;
    if (m == 0 && blockIdx.x < NROWS / 256)
        g_rowsum[blockIdx.x * 256 + threadIdx.x] = 0.0f;
    if (m == 0 && blockIdx.x == NROWS / 256 && threadIdx.x == 0) out[0] = 0.0f;
}

// ---------------- prefetch ----------------
__device__ __forceinline__ void prefetch_tile(int t, int buf, int tid, uint32_t sm0) {
    int m, bx, by;
    tdec(t, m, bx, by);
    int row0 = bx * TILE;
    int col0 = by * TILE;
    const int8_t* Bsrc = (m == 0) ? g_Nq : ((m == 1) ? g_Pq : g_Aq);
    int lr  = tid >> 1;
    int lc0 = tid & 1;
    int sw  = lr & 7;
    const int8_t* Ag = g_Aq + (size_t)(row0 + lr) * DDIM;
    const int8_t* Bg = Bsrc + (size_t)(col0 + lr) * DDIM;
    uint32_t sA = sm0 + (uint32_t)(buf * BUF_PAIR) + (uint32_t)(lr * 128);
    uint32_t sB = sA + 16384;
#pragma unroll
    for (int c = lc0; c < 8; c += 2) {
        CP_ASYNC16(sA + (uint32_t)((c ^ sw) << 4), Ag + c * 16);
        CP_ASYNC16(sB + (uint32_t)((c ^ sw) << 4), Bg + c * 16);
    }
    CP_COMMIT();
}

// ---------------- per-row-group epilogue ----------------
__device__ __forceinline__ void epi_quarter(const int acc[4][4], int mt,
                                            int warp_row0, int warp_col0,
                                            float coef, bool md, bool cm,
                                            float colacc[4][2],
                                            int rl, int cl, int lane) {
    int r_lo = warp_row0 + mt * 16 + rl;
    int r_hi = r_lo + 8;
    float e0 = 0.0f, e1 = 0.0f;
#pragma unroll
    for (int nt = 0; nt < 4; nt++) {
        int n0 = warp_col0 + nt * 8 + cl;
        float a0 = acc2arg(acc[nt][0]);
        float a1 = acc2arg(acc[nt][1]);
        float a2 = acc2arg(acc[nt][2]);
        float a3 = acc2arg(acc[nt][3]);
        if (md) {
            if (n0     == r_lo) a0 = DIAG2;
            if (n0 + 1 == r_lo) a1 = DIAG2;
            if (n0     == r_hi) a2 = DIAG2;
            if (n0 + 1 == r_hi) a3 = DIAG2;
        }
        float x0 = exp2f(a0), x1 = exp2f(a1), x2 = exp2f(a2), x3 = exp2f(a3);
        e0 += x0 + x1;
        e1 += x2 + x3;
        if (cm) {
            colacc[nt][0] += x0 + x2;
            colacc[nt][1] += x1 + x3;
        }
    }
    e0 += __shfl_xor_sync(0xffffffffu, e0, 1);
    e0 += __shfl_xor_sync(0xffffffffu, e0, 2);
    e1 += __shfl_xor_sync(0xffffffffu, e1, 1);
    e1 += __shfl_xor_sync(0xffffffffu, e1, 2);
    if ((lane & 3) == 0) {
        atomicAdd(&g_rowsum[r_lo], coef * e0);
        atomicAdd(&g_rowsum[r_hi], coef * e1);
    }
}

// ---------------- persistent GEMM+exp kernel ----------------
__global__ __launch_bounds__(THREADS) void gemm_exp_mma() {
    extern __shared__ char smem[];
    uint32_t sm0 = smem_u32(smem);

    int tid  = threadIdx.x;
    int lane = tid & 31;
    int wid  = tid >> 5;
    int wm   = wid >> 2;
    int wn   = wid & 3;

    int rA    = wm * 64 + (lane & 15);
    int halfA = lane >> 4;
    int a7    = rA & 7;
    int rB    = wn * 32 + ((lane >> 4) & 1) * 8 + (lane & 7);
    int halfB = (lane >> 3) & 1;
    int b7    = lane & 7;
    int rl = lane >> 2;
    int cl = (lane & 3) * 2;

    int t0 = blockIdx.x;
    prefetch_tile(t0, 0, tid, sm0);
    if (t0 + GRID_P < NTILES) prefetch_tile(t0 + GRID_P, 1, tid, sm0);

    int bufc = 0;
    for (int t = t0; t < NTILES; t += GRID_P) {
        if (t + GRID_P < NTILES) { CP_WAIT1(); } else { CP_WAIT0(); }
        __syncthreads();
        int t2 = t + 2 * GRID_P;
        if (t2 < NTILES) prefetch_tile(t2, (bufc + 2) % 3, tid, sm0);

        uint32_t sAu = sm0 + (uint32_t)(bufc * BUF_PAIR);
        uint32_t sBu = sAu + 16384;

        int m, bx, by;
        tdec(t, m, bx, by);
        float coef = (m == 0) ? 0.5f : 0.25f;
        bool md = (m >= 1) && (bx == by);
        bool cm = (m == 2) && (bx != by);      // symmetric pair: add col sums too
        int warp_row0 = bx * TILE + wm * 64;
        int warp_col0 = by * TILE + wn * 32;

        float colacc[4][2];
#pragma unroll
        for (int nt = 0; nt < 4; nt++) { colacc[nt][0] = 0.0f; colacc[nt][1] = 0.0f; }

#pragma unroll
        for (int s = 0; s < 2; s++) {
            int acc[2][4][4];
#pragma unroll
            for (int mh = 0; mh < 2; mh++)
#pragma unroll
                for (int nt = 0; nt < 4; nt++)
#pragma unroll
                    for (int v = 0; v < 4; v++) acc[mh][nt][v] = 0;

#pragma unroll
            for (int ks = 0; ks < 4; ks++) {
                uint32_t a[2][4], b[4][2];
#pragma unroll
                for (int mh = 0; mh < 2; mh++) {
                    int mt = s * 2 + mh;
                    uint32_t addr = sAu + (uint32_t)((rA + mt * 16) * 128)
                                  + (uint32_t)(((ks * 2 + halfA) ^ a7) << 4);
                    LDSM_X4(a[mh][0], a[mh][1], a[mh][2], a[mh][3], addr);
                }
#pragma unroll
                for (int p = 0; p < 2; p++) {
                    uint32_t addr = sBu + (uint32_t)((rB + p * 16) * 128)
                                  + (uint32_t)(((ks * 2 + halfB) ^ b7) << 4);
                    LDSM_X4(b[2*p][0], b[2*p][1], b[2*p+1][0], b[2*p+1][1], addr);
                }
#pragma unroll
                for (int mh = 0; mh < 2; mh++)
#pragma unroll
                    for (int nt = 0; nt < 4; nt++)
                        MMA_S8(acc[mh][nt], a[mh], b[nt]);
            }
#pragma unroll
            for (int mh = 0; mh < 2; mh++)
                epi_quarter(acc[mh], s * 2 + mh, warp_row0, warp_col0,
                            coef, md, cm, colacc, rl, cl, lane);
        }

        // flush column sums for symmetric pair tiles (rows of the by block)
        if (cm) {
#pragma unroll
            for (int nt = 0; nt < 4; nt++) {
                float c0 = colacc[nt][0], c1 = colacc[nt][1];
                c0 += __shfl_xor_sync(0xffffffffu, c0, 4);
                c1 += __shfl_xor_sync(0xffffffffu, c1, 4);
                c0 += __shfl_xor_sync(0xffffffffu, c0, 8);
                c1 += __shfl_xor_sync(0xffffffffu, c1, 8);
                c0 += __shfl_xor_sync(0xffffffffu, c0, 16);
                c1 += __shfl_xor_sync(0xffffffffu, c1, 16);
                if (lane < 4) {
                    int c = warp_col0 + nt * 8 + cl;
                    atomicAdd(&g_rowsum[c], coef * c0);
                    atomicAdd(&g_rowsum[c + 1], coef * c1);
                }
            }
        }
        bufc = (bufc == 2) ? 0 : bufc + 1;
    }
}

// ---------------- finalize: one warp per row (fp32 pos_sim) ----------------
__global__ __launch_bounds__(256) void finalize_k(const float* __restrict__ A,
                                                  const float* __restrict__ P,
                                                  float* out) {
    int tid  = threadIdx.x;
    int lane = tid & 31;
    int wid  = tid >> 5;
    int row  = blockIdx.x * 8 + wid;

    float4 a = *(const float4*)(A + (size_t)row * DDIM + lane * 4);
    float4 p = *(const float4*)(P + (size_t)row * DDIM + lane * 4);
    float dsum = a.x * p.x + a.y * p.y + a.z * p.z + a.w * p.w;
#pragma unroll
    for (int off = 16; off > 0; off >>= 1)
        dsum += __shfl_xor_sync(0xffffffffu, dsum, off);

    __shared__ float sh[8];
    if (lane == 0) {
        float v = logf(g_rowsum[row]) - dsum * INV_MAG;
        sh[wid] = v > 0.0f ? v : 0.0f;
    }
    __syncthreads();
    if (tid == 0) {
        float s = sh[0] + sh[1] + sh[2] + sh[3] + sh[4] + sh[5] + sh[6] + sh[7];
        atomicAdd(out, s * (1.0f / NROWS));
    }
}

extern "C" void kernel_launch(void* const* d_in, const int* in_sizes, int n_in,
                              void* d_out, int out_size) {
    const float* A  = (const float*)d_in[0];
    const float* P  = (const float*)d_in[1];
    const float* Ng = (const float*)d_in[2];
    float* out = (float*)d_out;

    static int smem_set = 0;
    if (!smem_set) {
        cudaFuncSetAttribute(gemm_exp_mma, cudaFuncAttributeMaxDynamicSharedMemorySize,
                             SM_TOTAL);
        smem_set = 1;
    }

    dim3 cg(NROWS * DDIM / 4 / 256, 3);          // (1024, 3)
    conv_k<<<cg, 256>>>(A, P, Ng, out);
    gemm_exp_mma<<<GRID_P, THREADS, SM_TOTAL>>>();
    finalize_k<<<NROWS / 8, 256>>>(A, P, out);   // 1024 blocks, warp per row
}